// round 16
// baseline (speedup 1.0000x reference)
#include <cuda_runtime.h>
#include <cuda_fp16.h>
#include <cstdint>

#define FULLM 0xffffffffu
#define DINLINE __device__ __forceinline__

constexpr int NN = 150000, CC = 256, LL = 50000, KTOP = 200;
constexpr int NU = NN - LL;
constexpr int SEGP = 704;              // 22 chunks of 32 rows
constexpr int NSEGP = 143;             // 143 * 704 = 100672 >= NU
constexpr int CHKP = 22;
constexpr int NPAD = NSEGP * SEGP;     // padded unlabeled rows (100672)
constexpr int NIMG = LL + NPAD;        // image rows (pad zero)
// xpt smem: A-hi double (2*10240) + B h+l double (2*20480) = 61440
constexpr int SMEM_MMA = 61440;
// ptx smem per stage: ph 16896 + xh 8704 + xl 8704 = 34304, x2 = 68608
constexpr int SMEM_PTX = 68608;

// ---------------- scratch (device globals; no allocation allowed) ------------
__device__ __align__(16) unsigned short g_prob16[(size_t)NU * CC];  // fp16 prob
__device__ float g_rnorm[NN];
__device__ float g_psum[CC * CC];
__device__ float g_protos[CC * CC];
__device__ float g_S[CC * CC];
__device__ float g_colsum[CC];
__device__ int   g_cntall[CC];
__device__ int   g_cntlab[CC];
// protoN as fp16 hi/lo smem-image: [chunk 8][hl 2][class 256][40 shorts (80B pitch)]
__device__ __align__(16) unsigned short g_Bimg[8 * 2 * 256 * 40];
// masked-p fp16 image [NPAD][256] (pad rows stay zero)
__device__ __align__(16) unsigned short g_Ph[(size_t)NPAD * CC];
// raw-x fp16 hi/lo images, GLOBAL row index [NIMG][256] (pad rows zero)
__device__ __align__(16) unsigned short g_Xh[(size_t)NIMG * CC];
__device__ __align__(16) unsigned short g_Xl[(size_t)NIMG * CC];

// ---------------- helpers ----------------------------------------------------
DINLINE float block_reduce_sum(float v) {
    __shared__ float red[8];
    __shared__ float tot;
    for (int o = 16; o; o >>= 1) v += __shfl_xor_sync(FULLM, v, o);
    if ((threadIdx.x & 31) == 0) red[threadIdx.x >> 5] = v;
    __syncthreads();
    if (threadIdx.x < 32) {
        float s = (threadIdx.x < 8) ? red[threadIdx.x] : 0.f;
        for (int o = 4; o; o >>= 1) s += __shfl_xor_sync(FULLM, s, o);
        if (threadIdx.x == 0) tot = s;
    }
    __syncthreads();
    return tot;
}
DINLINE uint32_t smem_u32(const void* p) {
    uint32_t a;
    asm("{ .reg .u64 t; cvta.to.shared.u64 t, %1; cvt.u32.u64 %0, t; }"
        : "=r"(a) : "l"(p));
    return a;
}
// fp16 split: h = fp16(v), l = fp16(v - h)
DINLINE void hsplit(float v, unsigned short& h, unsigned short& l) {
    __half hh = __float2half_rn(v);
    float hf = __half2float(hh);
    __half ll = __float2half_rn(v - hf);
    h = __half_as_ushort(hh);
    l = __half_as_ushort(ll);
}
DINLINE void cpasync16(uint32_t dst, const void* src) {
    asm volatile("cp.async.ca.shared.global [%0], [%1], 16;"
                 :: "r"(dst), "l"(src));
}
#define CP_COMMIT() asm volatile("cp.async.commit_group;" ::: "memory")
#define CP_WAIT0()  asm volatile("cp.async.wait_group 0;" ::: "memory")
#define CP_WAIT1()  asm volatile("cp.async.wait_group 1;" ::: "memory")

DINLINE void ldm_x4(uint32_t* r, uint32_t addr) {
    asm volatile("ldmatrix.sync.aligned.m8n8.x4.shared.b16 {%0,%1,%2,%3}, [%4];"
                 : "=r"(r[0]), "=r"(r[1]), "=r"(r[2]), "=r"(r[3]) : "r"(addr));
}
DINLINE void ldm_x2(uint32_t* r, uint32_t addr) {
    asm volatile("ldmatrix.sync.aligned.m8n8.x2.shared.b16 {%0,%1}, [%2];"
                 : "=r"(r[0]), "=r"(r[1]) : "r"(addr));
}
DINLINE void ldmT_x4(uint32_t* r, uint32_t addr) {
    asm volatile("ldmatrix.sync.aligned.m8n8.x4.trans.shared.b16 {%0,%1,%2,%3}, [%4];"
                 : "=r"(r[0]), "=r"(r[1]), "=r"(r[2]), "=r"(r[3]) : "r"(addr));
}
DINLINE void ldmT_x2(uint32_t* r, uint32_t addr) {
    asm volatile("ldmatrix.sync.aligned.m8n8.x2.trans.shared.b16 {%0,%1}, [%2];"
                 : "=r"(r[0]), "=r"(r[1]) : "r"(addr));
}
DINLINE void mma_f16(float* c, const uint32_t* a, const uint32_t* b) {
    asm volatile(
        "mma.sync.aligned.m16n8k16.row.col.f32.f16.f16.f32 "
        "{%0,%1,%2,%3}, {%4,%5,%6,%7}, {%8,%9}, {%0,%1,%2,%3};"
        : "+f"(c[0]), "+f"(c[1]), "+f"(c[2]), "+f"(c[3])
        : "r"(a[0]), "r"(a[1]), "r"(a[2]), "r"(a[3]), "r"(b[0]), "r"(b[1]));
}

// ---------------- kernel 0: zero accumulators --------------------------------
__global__ void zero_k() {
    int i = blockIdx.x * blockDim.x + threadIdx.x;
    if (i < CC * CC) { g_psum[i] = 0.f; g_S[i] = 0.f; }
    if (i < CC) { g_colsum[i] = 0.f; g_cntall[i] = 0; g_cntlab[i] = 0; }
}

// ---------------- kernel 1: cls, rnorm, hist, psum atomics, x fp16 image -----
__global__ void prep_k(const float* __restrict__ x, const float* __restrict__ labels) {
    __shared__ int s_all[CC], s_lab[CC];
    for (int i = threadIdx.x; i < CC; i += blockDim.x) { s_all[i] = 0; s_lab[i] = 0; }
    __syncthreads();
    int warp = threadIdx.x >> 5, lane = threadIdx.x & 31;
    int wpb = blockDim.x >> 5;
    for (int row = blockIdx.x * wpb + warp; row < NN; row += gridDim.x * wpb) {
        const float4* lr4 = (const float4*)(labels + (size_t)row * CC);
        int myc = -1;
        #pragma unroll
        for (int j = 0; j < 2; j++) {
            float4 lv = lr4[lane + 32 * j];
            int cb = 4 * (lane + 32 * j);
            if (lv.x > 0.5f) myc = cb + 0;
            if (lv.y > 0.5f) myc = cb + 1;
            if (lv.z > 0.5f) myc = cb + 2;
            if (lv.w > 0.5f) myc = cb + 3;
        }
        int cls = __reduce_max_sync(FULLM, myc);
        const float4* xr = (const float4*)(x + (size_t)row * CC);
        float ss = 0.f;
        float4 v[2];
        #pragma unroll
        for (int j = 0; j < 2; j++) {
            v[j] = xr[lane + 32 * j];
            ss += v[j].x * v[j].x + v[j].y * v[j].y + v[j].z * v[j].z + v[j].w * v[j].w;
        }
        for (int o = 16; o; o >>= 1) ss += __shfl_xor_sync(FULLM, ss, o);
        if (lane == 0) {
            g_rnorm[row] = rsqrtf(fmaxf(ss, 1e-12f));
            atomicAdd(&s_all[cls], 1);
            if (row < LL) atomicAdd(&s_lab[cls], 1);
        }
        if (row < LL) {   // fused per-class labeled feature sums
            float* ps = g_psum + cls * CC;
            #pragma unroll
            for (int j = 0; j < 2; j++) {
                int fb = 4 * (lane + 32 * j);
                atomicAdd(ps + fb + 0, v[j].x);
                atomicAdd(ps + fb + 1, v[j].y);
                atomicAdd(ps + fb + 2, v[j].z);
                atomicAdd(ps + fb + 3, v[j].w);
            }
        }
        // fp16 split image: hi for all rows; lo only for unlabeled (sole consumer)
        size_t ur = (size_t)row * CC;
        bool needL = row >= LL;
        #pragma unroll
        for (int j = 0; j < 2; j++) {
            int fb = 4 * (lane + 32 * j);
            unsigned short h[4], l[4];
            hsplit(v[j].x, h[0], l[0]);
            hsplit(v[j].y, h[1], l[1]);
            hsplit(v[j].z, h[2], l[2]);
            hsplit(v[j].w, h[3], l[3]);
            *(uint2*)(g_Xh + ur + fb) = *(uint2*)h;
            if (needL) *(uint2*)(g_Xl + ur + fb) = *(uint2*)l;
        }
    }
    __syncthreads();
    for (int i = threadIdx.x; i < CC; i += blockDim.x) {
        if (s_all[i]) atomicAdd(&g_cntall[i], s_all[i]);
        if (s_lab[i]) atomicAdd(&g_cntlab[i], s_lab[i]);
    }
}

// ---------------- write protoN split (fp16 hi/lo) into image -----------------
DINLINE void write_bimg(int c, int f, float v) {
    unsigned short h, l;
    hsplit(v, h, l);
    int ck = f >> 5, kl = f & 31;
    g_Bimg[((ck * 2 + 0) * 256 + c) * 40 + kl] = h;
    g_Bimg[((ck * 2 + 1) * 256 + c) * 40 + kl] = l;
}

// ---------------- kernel: protos + normalized protoN split -------------------
__global__ void pfin_k() {
    int c = blockIdx.x, f = threadIdx.x;
    float v = g_psum[c * CC + f] / (float)g_cntall[c];
    g_protos[c * CC + f] = v;
    float tot = block_reduce_sum(v * v);
    write_bimg(c, f, v * rsqrtf(fmaxf(tot, 1e-12f)));
}

// ---------------- fp16 2-product mma GEMM: OUT[n][c]=rnorm[n]*(X[n].pN[c]) ---
// block 128 rows x 128 classes (grid.y=2), 8 warps, warp tile 64x32, 2 CTA/SM.
template <bool H16>
__global__ void __launch_bounds__(256, 2)
gemm_mma_k(float* __restrict__ OUT, int imgoff, int nrows) {
    extern __shared__ char dsm[];
    __shared__ float s_rn[128];

    const int tid = threadIdx.x, lane = tid & 31, wid = tid >> 5;
    const int wm = wid >> 2, wn = wid & 3;
    const int n0 = blockIdx.x * 128;
    const int c0 = blockIdx.y * 128;

    const uint32_t uA0 = smem_u32(dsm);
    const uint32_t uA1 = uA0 + 10240;
    const uint32_t uB0 = uA0 + 20480;
    const uint32_t uB1 = uA0 + 40960;

    if (tid < 128) {
        int r = n0 + tid;
        s_rn[tid] = (r < nrows) ? g_rnorm[imgoff + r] : 0.f;
    }

    const int a_row = (lane & 7) + 8 * ((lane >> 3) & 1);
    const int a_kb  = 16 * (lane >> 4);
    const int b_row = lane & 7;
    const int b_kb  = 16 * ((lane >> 3) & 1);
    const uint32_t aoff = (uint32_t)((64 * wm + a_row) * 80 + a_kb);
    const uint32_t bofs = (uint32_t)((32 * wn + b_row) * 80 + b_kb);

    float acc[4][4][4];
    #pragma unroll
    for (int i = 0; i < 4; i++)
        #pragma unroll
        for (int j = 0; j < 4; j++)
            #pragma unroll
            for (int q = 0; q < 4; q++) acc[i][j][q] = 0.f;

    auto stageA = [&](uint32_t ub, int ckn) {
        #pragma unroll
        for (int s = 0; s < 2; s++) {
            int t = tid + 256 * s;
            int r = t >> 2, pc = t & 3;
            const unsigned short* src = g_Xh
                + (size_t)(imgoff + n0 + r) * CC + ckn * 32 + pc * 8;
            cpasync16(ub + (uint32_t)(r * 80 + pc * 16), src);
        }
    };
    auto stageB = [&](uint32_t ub, int ckn) {
        const char* srcH = (const char*)g_Bimg + (size_t)((ckn * 2 + 0) * 256 + c0) * 80;
        const char* srcL = (const char*)g_Bimg + (size_t)((ckn * 2 + 1) * 256 + c0) * 80;
        #pragma unroll
        for (int s = 0; s < 5; s++) {
            int j = tid + 256 * s;
            if (j < 640) cpasync16(ub + 16 * j, srcH + 16 * j);
            else         cpasync16(ub + 10240 + 16 * (j - 640), srcL + 16 * (j - 640));
        }
    };

    stageA(uA0, 0); stageB(uB0, 0); CP_COMMIT();

    for (int ck = 0; ck < 8; ck++) {
        uint32_t uAc = (ck & 1) ? uA1 : uA0;
        uint32_t uBc = (ck & 1) ? uB1 : uB0;
        if (ck < 7) {
            stageA((ck & 1) ? uA0 : uA1, ck + 1);
            stageB((ck & 1) ? uB0 : uB1, ck + 1);
            CP_COMMIT();
            CP_WAIT1();
        } else {
            CP_WAIT0();
        }
        __syncthreads();

        #pragma unroll
        for (int ks = 0; ks < 2; ks++) {
            uint32_t ah[4][4];
            #pragma unroll
            for (int mf = 0; mf < 4; mf++)
                ldm_x4(ah[mf], uAc + aoff + mf * 1280 + ks * 32);
            {
                uint32_t bh[4][2];
                #pragma unroll
                for (int nf = 0; nf < 4; nf++)
                    ldm_x2(bh[nf], uBc + bofs + nf * 640 + ks * 32);
                #pragma unroll
                for (int mf = 0; mf < 4; mf++)
                    #pragma unroll
                    for (int nf = 0; nf < 4; nf++)
                        mma_f16(acc[mf][nf], ah[mf], bh[nf]);
            }
            {
                uint32_t bl[4][2];
                #pragma unroll
                for (int nf = 0; nf < 4; nf++)
                    ldm_x2(bl[nf], uBc + 10240 + bofs + nf * 640 + ks * 32);
                #pragma unroll
                for (int mf = 0; mf < 4; mf++)
                    #pragma unroll
                    for (int nf = 0; nf < 4; nf++)
                        mma_f16(acc[mf][nf], ah[mf], bl[nf]);
            }
        }
        __syncthreads();
    }

    #pragma unroll
    for (int mf = 0; mf < 4; mf++) {
        #pragma unroll
        for (int half = 0; half < 2; half++) {
            int rl = 64 * wm + 16 * mf + (lane >> 2) + 8 * half;
            int grow = n0 + rl;
            if (grow < nrows) {
                float rs = s_rn[rl];
                if constexpr (H16) {
                    unsigned short* op = g_prob16 + (size_t)grow * CC
                                         + c0 + 32 * wn + 2 * (lane & 3);
                    #pragma unroll
                    for (int nf = 0; nf < 4; nf++) {
                        __half2 hv = __floats2half2_rn(acc[mf][nf][2 * half] * rs,
                                                       acc[mf][nf][2 * half + 1] * rs);
                        *(__half2*)(op + 8 * nf) = hv;
                    }
                } else {
                    float* op = OUT + (size_t)grow * CC + c0 + 32 * wn + 2 * (lane & 3);
                    #pragma unroll
                    for (int nf = 0; nf < 4; nf++) {
                        float2 v = make_float2(acc[mf][nf][2 * half] * rs,
                                               acc[mf][nf][2 * half + 1] * rs);
                        *(float2*)(op + 8 * nf) = v;
                    }
                }
            }
        }
    }
}

// ---------------- kernel: exact per-row top-k on fp16 keys -> Ph + colsum ----
__global__ void topk_k() {
    __shared__ float cs[CC];
    for (int i = threadIdx.x; i < CC; i += blockDim.x) cs[i] = 0.f;
    __syncthreads();
    int warp = threadIdx.x >> 5, lane = threadIdx.x & 31;
    for (int row = blockIdx.x * 8 + warp; row < NU; row += gridDim.x * 8) {
        const unsigned short* pr = g_prob16 + (size_t)row * CC;
        uint2 q0 = *(const uint2*)(pr + 4 * lane);
        uint2 q1 = *(const uint2*)(pr + 128 + 4 * lane);
        unsigned short hv[8] = {
            (unsigned short)(q0.x & 0xffff), (unsigned short)(q0.x >> 16),
            (unsigned short)(q0.y & 0xffff), (unsigned short)(q0.y >> 16),
            (unsigned short)(q1.x & 0xffff), (unsigned short)(q1.x >> 16),
            (unsigned short)(q1.y & 0xffff), (unsigned short)(q1.y >> 16) };
        unsigned key[8];
        #pragma unroll
        for (int j = 0; j < 8; j++) {
            unsigned s = hv[j];
            key[j] = (s & 0x8000u) ? (~s & 0xFFFFu) : (s | 0x8000u);
        }
        unsigned T = 0;
        for (int b = 15; b >= 0; b--) {
            unsigned cand = T | (1u << b);
            int cnt = 0;
            #pragma unroll
            for (int j = 0; j < 8; j++) cnt += (key[j] >= cand);
            cnt = (int)__reduce_add_sync(FULLM, (unsigned)cnt);
            if (cnt >= KTOP) {
                T = cand;
                if (cnt == KTOP) break;
            }
        }
        int gt = 0;
        #pragma unroll
        for (int j = 0; j < 8; j++) gt += (key[j] > T);
        gt = (int)__reduce_add_sync(FULLM, (unsigned)gt);
        int r = KTOP - gt;
        int cum = 0;
        unsigned short hq[8];
        #pragma unroll
        for (int j = 0; j < 8; j++) {
            bool eq = (key[j] == T);
            unsigned bal = __ballot_sync(FULLM, eq);
            int pre = cum + __popc(bal & ((1u << lane) - 1u));
            bool keep = (key[j] > T) || (eq && pre < r);
            cum += __popc(bal);
            hq[j] = keep ? hv[j] : (unsigned short)0;
            if (keep) {
                float o = __half2float(__ushort_as_half(hv[j]));
                if (o != 0.f) {
                    int cls = (j < 4) ? (4 * lane + j) : (128 + 4 * lane + (j - 4));
                    atomicAdd(&cs[cls], o);
                }
            }
        }
        unsigned short* ph = g_Ph + (size_t)row * CC;
        *(uint2*)(ph + 4 * lane)       = *(uint2*)(hq + 0);
        *(uint2*)(ph + 128 + 4 * lane) = *(uint2*)(hq + 4);
    }
    __syncthreads();
    float c = cs[threadIdx.x];
    if (c != 0.f) atomicAdd(&g_colsum[threadIdx.x], c);
}

// ---------------- split-K fp16 2-product GEMM: S[c][f]+=sum_r p[r][c]x[r][f] -
__global__ void __launch_bounds__(512, 1)
gemm_ptx_mma_k() {
    extern __shared__ char dsm[];
    const uint32_t uS0 = smem_u32(dsm);
    const uint32_t uS1 = uS0 + 34304;

    const int tid = threadIdx.x, lane = tid & 31, wid = tid >> 5;
    const int wm = wid >> 2, wn = wid & 3;
    const int f0 = blockIdx.y * 128;
    const int R0 = blockIdx.x * SEGP;

    auto stage = [&](uint32_t ub, int ck) {
        int r0 = R0 + ck * 32;
        #pragma unroll
        for (int s = 0; s < 4; s++) {
            int t = tid + 512 * s;
            if (t < 1024) {
                int r = t >> 5, piece = t & 31;
                const char* src = (const char*)g_Ph
                                  + (size_t)(r0 + r) * 512 + piece * 16;
                cpasync16(ub + r * 528 + piece * 16, src);
            } else if (t < 1536) {
                int t2 = t - 1024;
                int r = t2 >> 4, piece = t2 & 15;
                const char* src = (const char*)g_Xh
                                  + (size_t)(LL + r0 + r) * 512 + f0 * 2 + piece * 16;
                cpasync16(ub + 16896 + r * 272 + piece * 16, src);
            } else {
                int t2 = t - 1536;
                int r = t2 >> 4, piece = t2 & 15;
                const char* src = (const char*)g_Xl
                                  + (size_t)(LL + r0 + r) * 512 + f0 * 2 + piece * 16;
                cpasync16(ub + 25600 + r * 272 + piece * 16, src);
            }
        }
        CP_COMMIT();
    };

    const int krA = (lane & 7) + 8 * ((lane >> 4) & 1);
    const int cmA = 64 * wm + 8 * ((lane >> 3) & 1);
    const int krB = (lane & 7) + 8 * ((lane >> 3) & 1);
    const uint32_t aoff = (uint32_t)(krA * 528 + 2 * cmA);
    const uint32_t boff = (uint32_t)(krB * 272 + 2 * (32 * wn));

    float acc[4][4][4];
    #pragma unroll
    for (int i = 0; i < 4; i++)
        #pragma unroll
        for (int j = 0; j < 4; j++)
            #pragma unroll
            for (int q = 0; q < 4; q++) acc[i][j][q] = 0.f;

    stage(uS0, 0);

    for (int ck = 0; ck < CHKP; ck++) {
        if (ck + 1 < CHKP) {
            stage((ck & 1) ? uS0 : uS1, ck + 1);
            CP_WAIT1();
        } else {
            CP_WAIT0();
        }
        __syncthreads();

        uint32_t uP = (ck & 1) ? uS1 : uS0;
        uint32_t uXh = uP + 16896;
        uint32_t uXl = uP + 25600;
        #pragma unroll
        for (int ks = 0; ks < 2; ks++) {
            uint32_t ah[4][4];
            #pragma unroll
            for (int mf = 0; mf < 4; mf++)
                ldmT_x4(ah[mf], uP + (uint32_t)(ks * 16 * 528) + aoff + 2 * (16 * mf));
            {
                uint32_t bh[4][2];
                #pragma unroll
                for (int nf = 0; nf < 4; nf++)
                    ldmT_x2(bh[nf], uXh + (uint32_t)(ks * 16 * 272) + boff + 2 * (8 * nf));
                #pragma unroll
                for (int mf = 0; mf < 4; mf++)
                    #pragma unroll
                    for (int nf = 0; nf < 4; nf++)
                        mma_f16(acc[mf][nf], ah[mf], bh[nf]);
            }
            {
                uint32_t bl[4][2];
                #pragma unroll
                for (int nf = 0; nf < 4; nf++)
                    ldmT_x2(bl[nf], uXl + (uint32_t)(ks * 16 * 272) + boff + 2 * (8 * nf));
                #pragma unroll
                for (int mf = 0; mf < 4; mf++)
                    #pragma unroll
                    for (int nf = 0; nf < 4; nf++)
                        mma_f16(acc[mf][nf], ah[mf], bl[nf]);
            }
        }
        __syncthreads();
    }

    #pragma unroll
    for (int mf = 0; mf < 4; mf++) {
        #pragma unroll
        for (int nf = 0; nf < 4; nf++) {
            #pragma unroll
            for (int half = 0; half < 2; half++) {
                int c = 64 * wm + 16 * mf + (lane >> 2) + 8 * half;
                int f = f0 + 32 * wn + 8 * nf + 2 * (lane & 3);
                atomicAdd(&g_S[c * CC + f + 0], acc[mf][nf][2 * half + 0]);
                atomicAdd(&g_S[c * CC + f + 1], acc[mf][nf][2 * half + 1]);
            }
        }
    }
}

// ---------------- kernel: proto update + renorm + split write ----------------
__global__ void pfin2_k() {
    int c = blockIdx.x, f = threadIdx.x;
    float cp = g_colsum[c];
    float denom = cp + (float)g_cntlab[c];
    float pv = g_protos[c * CC + f];
    float nv = pv + g_S[c * CC + f] / denom - (cp / denom) * pv;
    float tot = block_reduce_sum(nv * nv);
    write_bimg(c, f, nv * rsqrtf(fmaxf(tot, 1e-12f)));
}

// ---------------- launch ------------------------------------------------------
extern "C" void kernel_launch(void* const* d_in, const int* in_sizes, int n_in,
                              void* d_out, int out_size) {
    (void)in_sizes; (void)n_in; (void)out_size;
    const float* x = (const float*)d_in[0];
    const float* labels = (const float*)d_in[1];
    float* out = (float*)d_out;

    cudaFuncSetAttribute(gemm_mma_k<true>,
                         cudaFuncAttributeMaxDynamicSharedMemorySize, SMEM_MMA);
    cudaFuncSetAttribute(gemm_mma_k<false>,
                         cudaFuncAttributeMaxDynamicSharedMemorySize, SMEM_MMA);
    cudaFuncSetAttribute(gemm_ptx_mma_k,
                         cudaFuncAttributeMaxDynamicSharedMemorySize, SMEM_PTX);

    zero_k<<<CC, 256>>>();                                    // 1
    prep_k<<<1480, 256>>>(x, labels);                         // 2
    pfin_k<<<CC, 256>>>();                                    // 3
    gemm_mma_k<true><<<dim3((NU + 127) / 128, 2), 256, SMEM_MMA>>>( // 4 (prob fp16)
        nullptr, LL, NU);
    topk_k<<<1563, 256>>>();                                  // 5
    gemm_ptx_mma_k<<<dim3(NSEGP, 2), 512, SMEM_PTX>>>();      // 6 (full wave now)
    pfin2_k<<<CC, 256>>>();                                   // 7
    gemm_mma_k<false><<<dim3((NN + 127) / 128, 2), 256, SMEM_MMA>>>(out, 0, NN); // 8
}

// round 17
// speedup vs baseline: 1.0268x; 1.0268x over previous
#include <cuda_runtime.h>
#include <cuda_fp16.h>
#include <cstdint>

#define FULLM 0xffffffffu
#define DINLINE __device__ __forceinline__

constexpr int NN = 150000, CC = 256, LL = 50000, KTOP = 200;
constexpr int NU = NN - LL;
constexpr int SEGP = 1376;             // 43 chunks of 32 rows
constexpr int NSEGP = 73;              // 73 * 1376 = 100448 >= NU (one full wave)
constexpr int CHKP = 43;
constexpr int NPAD = NSEGP * SEGP;     // padded unlabeled rows
constexpr int NIMG = LL + NPAD;        // image rows (pad zero)
// xpt smem: A-hi double (2*10240) + B h+l double (2*20480) = 61440
constexpr int SMEM_MMA = 61440;
// ptx smem per stage: ph 16896 + xh 8704 + xl 8704 = 34304, x2 = 68608
constexpr int SMEM_PTX = 68608;

// ---------------- scratch (device globals; no allocation allowed) ------------
__device__ __align__(16) unsigned short g_prob16[(size_t)NU * CC];  // fp16 prob
__device__ float g_rnorm[NN];
__device__ float g_psum[CC * CC];
__device__ float g_protos[CC * CC];
__device__ float g_S[CC * CC];
__device__ float g_colsum[CC];
__device__ int   g_cntall[CC];
__device__ int   g_cntlab[CC];
// protoN as fp16 hi/lo smem-image: [chunk 8][hl 2][class 256][40 shorts (80B pitch)]
__device__ __align__(16) unsigned short g_Bimg[8 * 2 * 256 * 40];
// masked-p fp16 image [NPAD][256] (pad rows stay zero)
__device__ __align__(16) unsigned short g_Ph[(size_t)NPAD * CC];
// raw-x fp16 hi/lo images, GLOBAL row index [NIMG][256] (pad rows zero)
__device__ __align__(16) unsigned short g_Xh[(size_t)NIMG * CC];
__device__ __align__(16) unsigned short g_Xl[(size_t)NIMG * CC];

// ---------------- helpers ----------------------------------------------------
DINLINE float block_reduce_sum(float v) {
    __shared__ float red[8];
    __shared__ float tot;
    for (int o = 16; o; o >>= 1) v += __shfl_xor_sync(FULLM, v, o);
    if ((threadIdx.x & 31) == 0) red[threadIdx.x >> 5] = v;
    __syncthreads();
    if (threadIdx.x < 32) {
        float s = (threadIdx.x < 8) ? red[threadIdx.x] : 0.f;
        for (int o = 4; o; o >>= 1) s += __shfl_xor_sync(FULLM, s, o);
        if (threadIdx.x == 0) tot = s;
    }
    __syncthreads();
    return tot;
}
DINLINE uint32_t smem_u32(const void* p) {
    uint32_t a;
    asm("{ .reg .u64 t; cvta.to.shared.u64 t, %1; cvt.u32.u64 %0, t; }"
        : "=r"(a) : "l"(p));
    return a;
}
// fp16 split: h = fp16(v), l = fp16(v - h)
DINLINE void hsplit(float v, unsigned short& h, unsigned short& l) {
    __half hh = __float2half_rn(v);
    float hf = __half2float(hh);
    __half ll = __float2half_rn(v - hf);
    h = __half_as_ushort(hh);
    l = __half_as_ushort(ll);
}
DINLINE void cpasync16(uint32_t dst, const void* src) {
    asm volatile("cp.async.ca.shared.global [%0], [%1], 16;"
                 :: "r"(dst), "l"(src));
}
#define CP_COMMIT() asm volatile("cp.async.commit_group;" ::: "memory")
#define CP_WAIT0()  asm volatile("cp.async.wait_group 0;" ::: "memory")
#define CP_WAIT1()  asm volatile("cp.async.wait_group 1;" ::: "memory")

DINLINE void ldm_x4(uint32_t* r, uint32_t addr) {
    asm volatile("ldmatrix.sync.aligned.m8n8.x4.shared.b16 {%0,%1,%2,%3}, [%4];"
                 : "=r"(r[0]), "=r"(r[1]), "=r"(r[2]), "=r"(r[3]) : "r"(addr));
}
DINLINE void ldm_x2(uint32_t* r, uint32_t addr) {
    asm volatile("ldmatrix.sync.aligned.m8n8.x2.shared.b16 {%0,%1}, [%2];"
                 : "=r"(r[0]), "=r"(r[1]) : "r"(addr));
}
DINLINE void ldmT_x4(uint32_t* r, uint32_t addr) {
    asm volatile("ldmatrix.sync.aligned.m8n8.x4.trans.shared.b16 {%0,%1,%2,%3}, [%4];"
                 : "=r"(r[0]), "=r"(r[1]), "=r"(r[2]), "=r"(r[3]) : "r"(addr));
}
DINLINE void ldmT_x2(uint32_t* r, uint32_t addr) {
    asm volatile("ldmatrix.sync.aligned.m8n8.x2.trans.shared.b16 {%0,%1}, [%2];"
                 : "=r"(r[0]), "=r"(r[1]) : "r"(addr));
}
DINLINE void mma_f16(float* c, const uint32_t* a, const uint32_t* b) {
    asm volatile(
        "mma.sync.aligned.m16n8k16.row.col.f32.f16.f16.f32 "
        "{%0,%1,%2,%3}, {%4,%5,%6,%7}, {%8,%9}, {%0,%1,%2,%3};"
        : "+f"(c[0]), "+f"(c[1]), "+f"(c[2]), "+f"(c[3])
        : "r"(a[0]), "r"(a[1]), "r"(a[2]), "r"(a[3]), "r"(b[0]), "r"(b[1]));
}

// ---------------- kernel 0: zero prep-time accumulators ----------------------
__global__ void zero_k() {
    int i = blockIdx.x * blockDim.x + threadIdx.x;
    if (i < CC * CC) g_psum[i] = 0.f;
    if (i < CC) { g_cntall[i] = 0; g_cntlab[i] = 0; }
}

// ---------------- kernel 1: cls, rnorm, hist, psum atomics, x fp16 image -----
__global__ void prep_k(const float* __restrict__ x, const float* __restrict__ labels) {
    __shared__ int s_all[CC], s_lab[CC];
    for (int i = threadIdx.x; i < CC; i += blockDim.x) { s_all[i] = 0; s_lab[i] = 0; }
    __syncthreads();
    int warp = threadIdx.x >> 5, lane = threadIdx.x & 31;
    int wpb = blockDim.x >> 5;
    for (int row = blockIdx.x * wpb + warp; row < NN; row += gridDim.x * wpb) {
        const float4* lr4 = (const float4*)(labels + (size_t)row * CC);
        int myc = -1;
        #pragma unroll
        for (int j = 0; j < 2; j++) {
            float4 lv = lr4[lane + 32 * j];
            int cb = 4 * (lane + 32 * j);
            if (lv.x > 0.5f) myc = cb + 0;
            if (lv.y > 0.5f) myc = cb + 1;
            if (lv.z > 0.5f) myc = cb + 2;
            if (lv.w > 0.5f) myc = cb + 3;
        }
        int cls = __reduce_max_sync(FULLM, myc);
        const float4* xr = (const float4*)(x + (size_t)row * CC);
        float ss = 0.f;
        float4 v[2];
        #pragma unroll
        for (int j = 0; j < 2; j++) {
            v[j] = xr[lane + 32 * j];
            ss += v[j].x * v[j].x + v[j].y * v[j].y + v[j].z * v[j].z + v[j].w * v[j].w;
        }
        for (int o = 16; o; o >>= 1) ss += __shfl_xor_sync(FULLM, ss, o);
        if (lane == 0) {
            g_rnorm[row] = rsqrtf(fmaxf(ss, 1e-12f));
            atomicAdd(&s_all[cls], 1);
            if (row < LL) atomicAdd(&s_lab[cls], 1);
        }
        if (row < LL) {   // fused per-class labeled feature sums
            float* ps = g_psum + cls * CC;
            #pragma unroll
            for (int j = 0; j < 2; j++) {
                int fb = 4 * (lane + 32 * j);
                atomicAdd(ps + fb + 0, v[j].x);
                atomicAdd(ps + fb + 1, v[j].y);
                atomicAdd(ps + fb + 2, v[j].z);
                atomicAdd(ps + fb + 3, v[j].w);
            }
        }
        // fp16 split image: hi for all rows; lo only for unlabeled (sole consumer)
        size_t ur = (size_t)row * CC;
        bool needL = row >= LL;
        #pragma unroll
        for (int j = 0; j < 2; j++) {
            int fb = 4 * (lane + 32 * j);
            unsigned short h[4], l[4];
            hsplit(v[j].x, h[0], l[0]);
            hsplit(v[j].y, h[1], l[1]);
            hsplit(v[j].z, h[2], l[2]);
            hsplit(v[j].w, h[3], l[3]);
            *(uint2*)(g_Xh + ur + fb) = *(uint2*)h;
            if (needL) *(uint2*)(g_Xl + ur + fb) = *(uint2*)l;
        }
    }
    __syncthreads();
    for (int i = threadIdx.x; i < CC; i += blockDim.x) {
        if (s_all[i]) atomicAdd(&g_cntall[i], s_all[i]);
        if (s_lab[i]) atomicAdd(&g_cntlab[i], s_lab[i]);
    }
}

// ---------------- write protoN split (fp16 hi/lo) into image -----------------
DINLINE void write_bimg(int c, int f, float v) {
    unsigned short h, l;
    hsplit(v, h, l);
    int ck = f >> 5, kl = f & 31;
    g_Bimg[((ck * 2 + 0) * 256 + c) * 40 + kl] = h;
    g_Bimg[((ck * 2 + 1) * 256 + c) * 40 + kl] = l;
}

// ---------------- kernel: protos + protoN split + zero S/colsum --------------
__global__ void pfin_k() {
    int c = blockIdx.x, f = threadIdx.x;
    // fold downstream accumulator zeroing here (runs before topk / gemm_ptx)
    g_S[c * CC + f] = 0.f;
    if (f == 0) g_colsum[c] = 0.f;
    float v = g_psum[c * CC + f] / (float)g_cntall[c];
    g_protos[c * CC + f] = v;
    float tot = block_reduce_sum(v * v);
    write_bimg(c, f, v * rsqrtf(fmaxf(tot, 1e-12f)));
}

// ---------------- fp16 2-product mma GEMM: OUT[n][c]=rnorm[n]*(X[n].pN[c]) ---
// block 128 rows x 128 classes (grid.y=2), 8 warps, warp tile 64x32, 2 CTA/SM.
template <bool H16>
__global__ void __launch_bounds__(256, 2)
gemm_mma_k(float* __restrict__ OUT, int imgoff, int nrows) {
    extern __shared__ char dsm[];
    __shared__ float s_rn[128];

    const int tid = threadIdx.x, lane = tid & 31, wid = tid >> 5;
    const int wm = wid >> 2, wn = wid & 3;
    const int n0 = blockIdx.x * 128;
    const int c0 = blockIdx.y * 128;

    const uint32_t uA0 = smem_u32(dsm);
    const uint32_t uA1 = uA0 + 10240;
    const uint32_t uB0 = uA0 + 20480;
    const uint32_t uB1 = uA0 + 40960;

    if (tid < 128) {
        int r = n0 + tid;
        s_rn[tid] = (r < nrows) ? g_rnorm[imgoff + r] : 0.f;
    }

    const int a_row = (lane & 7) + 8 * ((lane >> 3) & 1);
    const int a_kb  = 16 * (lane >> 4);
    const int b_row = lane & 7;
    const int b_kb  = 16 * ((lane >> 3) & 1);
    const uint32_t aoff = (uint32_t)((64 * wm + a_row) * 80 + a_kb);
    const uint32_t bofs = (uint32_t)((32 * wn + b_row) * 80 + b_kb);

    float acc[4][4][4];
    #pragma unroll
    for (int i = 0; i < 4; i++)
        #pragma unroll
        for (int j = 0; j < 4; j++)
            #pragma unroll
            for (int q = 0; q < 4; q++) acc[i][j][q] = 0.f;

    auto stageA = [&](uint32_t ub, int ckn) {
        #pragma unroll
        for (int s = 0; s < 2; s++) {
            int t = tid + 256 * s;
            int r = t >> 2, pc = t & 3;
            const unsigned short* src = g_Xh
                + (size_t)(imgoff + n0 + r) * CC + ckn * 32 + pc * 8;
            cpasync16(ub + (uint32_t)(r * 80 + pc * 16), src);
        }
    };
    auto stageB = [&](uint32_t ub, int ckn) {
        const char* srcH = (const char*)g_Bimg + (size_t)((ckn * 2 + 0) * 256 + c0) * 80;
        const char* srcL = (const char*)g_Bimg + (size_t)((ckn * 2 + 1) * 256 + c0) * 80;
        #pragma unroll
        for (int s = 0; s < 5; s++) {
            int j = tid + 256 * s;
            if (j < 640) cpasync16(ub + 16 * j, srcH + 16 * j);
            else         cpasync16(ub + 10240 + 16 * (j - 640), srcL + 16 * (j - 640));
        }
    };

    stageA(uA0, 0); stageB(uB0, 0); CP_COMMIT();

    for (int ck = 0; ck < 8; ck++) {
        uint32_t uAc = (ck & 1) ? uA1 : uA0;
        uint32_t uBc = (ck & 1) ? uB1 : uB0;
        if (ck < 7) {
            stageA((ck & 1) ? uA0 : uA1, ck + 1);
            stageB((ck & 1) ? uB0 : uB1, ck + 1);
            CP_COMMIT();
            CP_WAIT1();
        } else {
            CP_WAIT0();
        }
        __syncthreads();

        #pragma unroll
        for (int ks = 0; ks < 2; ks++) {
            uint32_t ah[4][4];
            #pragma unroll
            for (int mf = 0; mf < 4; mf++)
                ldm_x4(ah[mf], uAc + aoff + mf * 1280 + ks * 32);
            {
                uint32_t bh[4][2];
                #pragma unroll
                for (int nf = 0; nf < 4; nf++)
                    ldm_x2(bh[nf], uBc + bofs + nf * 640 + ks * 32);
                #pragma unroll
                for (int mf = 0; mf < 4; mf++)
                    #pragma unroll
                    for (int nf = 0; nf < 4; nf++)
                        mma_f16(acc[mf][nf], ah[mf], bh[nf]);
            }
            {
                uint32_t bl[4][2];
                #pragma unroll
                for (int nf = 0; nf < 4; nf++)
                    ldm_x2(bl[nf], uBc + 10240 + bofs + nf * 640 + ks * 32);
                #pragma unroll
                for (int mf = 0; mf < 4; mf++)
                    #pragma unroll
                    for (int nf = 0; nf < 4; nf++)
                        mma_f16(acc[mf][nf], ah[mf], bl[nf]);
            }
        }
        __syncthreads();
    }

    #pragma unroll
    for (int mf = 0; mf < 4; mf++) {
        #pragma unroll
        for (int half = 0; half < 2; half++) {
            int rl = 64 * wm + 16 * mf + (lane >> 2) + 8 * half;
            int grow = n0 + rl;
            if (grow < nrows) {
                float rs = s_rn[rl];
                if constexpr (H16) {
                    unsigned short* op = g_prob16 + (size_t)grow * CC
                                         + c0 + 32 * wn + 2 * (lane & 3);
                    #pragma unroll
                    for (int nf = 0; nf < 4; nf++) {
                        __half2 hv = __floats2half2_rn(acc[mf][nf][2 * half] * rs,
                                                       acc[mf][nf][2 * half + 1] * rs);
                        *(__half2*)(op + 8 * nf) = hv;
                    }
                } else {
                    float* op = OUT + (size_t)grow * CC + c0 + 32 * wn + 2 * (lane & 3);
                    #pragma unroll
                    for (int nf = 0; nf < 4; nf++) {
                        float2 v = make_float2(acc[mf][nf][2 * half] * rs,
                                               acc[mf][nf][2 * half + 1] * rs);
                        *(float2*)(op + 8 * nf) = v;
                    }
                }
            }
        }
    }
}

// ---------------- kernel: exact per-row top-k on fp16 keys -> Ph + colsum ----
__global__ void topk_k() {
    __shared__ float cs[CC];
    for (int i = threadIdx.x; i < CC; i += blockDim.x) cs[i] = 0.f;
    __syncthreads();
    int warp = threadIdx.x >> 5, lane = threadIdx.x & 31;
    for (int row = blockIdx.x * 8 + warp; row < NU; row += gridDim.x * 8) {
        const unsigned short* pr = g_prob16 + (size_t)row * CC;
        uint2 q0 = *(const uint2*)(pr + 4 * lane);
        uint2 q1 = *(const uint2*)(pr + 128 + 4 * lane);
        unsigned short hv[8] = {
            (unsigned short)(q0.x & 0xffff), (unsigned short)(q0.x >> 16),
            (unsigned short)(q0.y & 0xffff), (unsigned short)(q0.y >> 16),
            (unsigned short)(q1.x & 0xffff), (unsigned short)(q1.x >> 16),
            (unsigned short)(q1.y & 0xffff), (unsigned short)(q1.y >> 16) };
        unsigned key[8];
        #pragma unroll
        for (int j = 0; j < 8; j++) {
            unsigned s = hv[j];
            key[j] = (s & 0x8000u) ? (~s & 0xFFFFu) : (s | 0x8000u);
        }
        unsigned T = 0;
        for (int b = 15; b >= 0; b--) {
            unsigned cand = T | (1u << b);
            int cnt = 0;
            #pragma unroll
            for (int j = 0; j < 8; j++) cnt += (key[j] >= cand);
            cnt = (int)__reduce_add_sync(FULLM, (unsigned)cnt);
            if (cnt >= KTOP) {
                T = cand;
                if (cnt == KTOP) break;
            }
        }
        int gt = 0;
        #pragma unroll
        for (int j = 0; j < 8; j++) gt += (key[j] > T);
        gt = (int)__reduce_add_sync(FULLM, (unsigned)gt);
        int r = KTOP - gt;
        int cum = 0;
        unsigned short hq[8];
        #pragma unroll
        for (int j = 0; j < 8; j++) {
            bool eq = (key[j] == T);
            unsigned bal = __ballot_sync(FULLM, eq);
            int pre = cum + __popc(bal & ((1u << lane) - 1u));
            bool keep = (key[j] > T) || (eq && pre < r);
            cum += __popc(bal);
            hq[j] = keep ? hv[j] : (unsigned short)0;
            if (keep) {
                float o = __half2float(__ushort_as_half(hv[j]));
                if (o != 0.f) {
                    int cls = (j < 4) ? (4 * lane + j) : (128 + 4 * lane + (j - 4));
                    atomicAdd(&cs[cls], o);
                }
            }
        }
        unsigned short* ph = g_Ph + (size_t)row * CC;
        *(uint2*)(ph + 4 * lane)       = *(uint2*)(hq + 0);
        *(uint2*)(ph + 128 + 4 * lane) = *(uint2*)(hq + 4);
    }
    __syncthreads();
    float c = cs[threadIdx.x];
    if (c != 0.f) atomicAdd(&g_colsum[threadIdx.x], c);
}

// ---------------- split-K fp16 2-product GEMM: S[c][f]+=sum_r p[r][c]x[r][f] -
__global__ void __launch_bounds__(512, 1)
gemm_ptx_mma_k() {
    extern __shared__ char dsm[];
    const uint32_t uS0 = smem_u32(dsm);
    const uint32_t uS1 = uS0 + 34304;

    const int tid = threadIdx.x, lane = tid & 31, wid = tid >> 5;
    const int wm = wid >> 2, wn = wid & 3;
    const int f0 = blockIdx.y * 128;
    const int R0 = blockIdx.x * SEGP;

    auto stage = [&](uint32_t ub, int ck) {
        int r0 = R0 + ck * 32;
        #pragma unroll
        for (int s = 0; s < 4; s++) {
            int t = tid + 512 * s;
            if (t < 1024) {
                int r = t >> 5, piece = t & 31;
                const char* src = (const char*)g_Ph
                                  + (size_t)(r0 + r) * 512 + piece * 16;
                cpasync16(ub + r * 528 + piece * 16, src);
            } else if (t < 1536) {
                int t2 = t - 1024;
                int r = t2 >> 4, piece = t2 & 15;
                const char* src = (const char*)g_Xh
                                  + (size_t)(LL + r0 + r) * 512 + f0 * 2 + piece * 16;
                cpasync16(ub + 16896 + r * 272 + piece * 16, src);
            } else {
                int t2 = t - 1536;
                int r = t2 >> 4, piece = t2 & 15;
                const char* src = (const char*)g_Xl
                                  + (size_t)(LL + r0 + r) * 512 + f0 * 2 + piece * 16;
                cpasync16(ub + 25600 + r * 272 + piece * 16, src);
            }
        }
        CP_COMMIT();
    };

    const int krA = (lane & 7) + 8 * ((lane >> 4) & 1);
    const int cmA = 64 * wm + 8 * ((lane >> 3) & 1);
    const int krB = (lane & 7) + 8 * ((lane >> 3) & 1);
    const uint32_t aoff = (uint32_t)(krA * 528 + 2 * cmA);
    const uint32_t boff = (uint32_t)(krB * 272 + 2 * (32 * wn));

    float acc[4][4][4];
    #pragma unroll
    for (int i = 0; i < 4; i++)
        #pragma unroll
        for (int j = 0; j < 4; j++)
            #pragma unroll
            for (int q = 0; q < 4; q++) acc[i][j][q] = 0.f;

    stage(uS0, 0);

    for (int ck = 0; ck < CHKP; ck++) {
        if (ck + 1 < CHKP) {
            stage((ck & 1) ? uS0 : uS1, ck + 1);
            CP_WAIT1();
        } else {
            CP_WAIT0();
        }
        __syncthreads();

        uint32_t uP = (ck & 1) ? uS1 : uS0;
        uint32_t uXh = uP + 16896;
        uint32_t uXl = uP + 25600;
        #pragma unroll
        for (int ks = 0; ks < 2; ks++) {
            uint32_t ah[4][4];
            #pragma unroll
            for (int mf = 0; mf < 4; mf++)
                ldmT_x4(ah[mf], uP + (uint32_t)(ks * 16 * 528) + aoff + 2 * (16 * mf));
            {
                uint32_t bh[4][2];
                #pragma unroll
                for (int nf = 0; nf < 4; nf++)
                    ldmT_x2(bh[nf], uXh + (uint32_t)(ks * 16 * 272) + boff + 2 * (8 * nf));
                #pragma unroll
                for (int mf = 0; mf < 4; mf++)
                    #pragma unroll
                    for (int nf = 0; nf < 4; nf++)
                        mma_f16(acc[mf][nf], ah[mf], bh[nf]);
            }
            {
                uint32_t bl[4][2];
                #pragma unroll
                for (int nf = 0; nf < 4; nf++)
                    ldmT_x2(bl[nf], uXl + (uint32_t)(ks * 16 * 272) + boff + 2 * (8 * nf));
                #pragma unroll
                for (int mf = 0; mf < 4; mf++)
                    #pragma unroll
                    for (int nf = 0; nf < 4; nf++)
                        mma_f16(acc[mf][nf], ah[mf], bl[nf]);
            }
        }
        __syncthreads();
    }

    #pragma unroll
    for (int mf = 0; mf < 4; mf++) {
        #pragma unroll
        for (int nf = 0; nf < 4; nf++) {
            #pragma unroll
            for (int half = 0; half < 2; half++) {
                int c = 64 * wm + 16 * mf + (lane >> 2) + 8 * half;
                int f = f0 + 32 * wn + 8 * nf + 2 * (lane & 3);
                atomicAdd(&g_S[c * CC + f + 0], acc[mf][nf][2 * half + 0]);
                atomicAdd(&g_S[c * CC + f + 1], acc[mf][nf][2 * half + 1]);
            }
        }
    }
}

// ---------------- kernel: proto update + renorm + split write ----------------
__global__ void pfin2_k() {
    int c = blockIdx.x, f = threadIdx.x;
    float cp = g_colsum[c];
    float denom = cp + (float)g_cntlab[c];
    float pv = g_protos[c * CC + f];
    float nv = pv + g_S[c * CC + f] / denom - (cp / denom) * pv;
    float tot = block_reduce_sum(nv * nv);
    write_bimg(c, f, nv * rsqrtf(fmaxf(tot, 1e-12f)));
}

// ---------------- launch ------------------------------------------------------
extern "C" void kernel_launch(void* const* d_in, const int* in_sizes, int n_in,
                              void* d_out, int out_size) {
    (void)in_sizes; (void)n_in; (void)out_size;
    const float* x = (const float*)d_in[0];
    const float* labels = (const float*)d_in[1];
    float* out = (float*)d_out;

    cudaFuncSetAttribute(gemm_mma_k<true>,
                         cudaFuncAttributeMaxDynamicSharedMemorySize, SMEM_MMA);
    cudaFuncSetAttribute(gemm_mma_k<false>,
                         cudaFuncAttributeMaxDynamicSharedMemorySize, SMEM_MMA);
    cudaFuncSetAttribute(gemm_ptx_mma_k,
                         cudaFuncAttributeMaxDynamicSharedMemorySize, SMEM_PTX);

    zero_k<<<CC, 256>>>();                                    // 1
    prep_k<<<1480, 256>>>(x, labels);                         // 2
    pfin_k<<<CC, 256>>>();                                    // 3 (+S/colsum zero)
    gemm_mma_k<true><<<dim3((NU + 127) / 128, 2), 256, SMEM_MMA>>>( // 4 (prob fp16)
        nullptr, LL, NU);
    topk_k<<<1563, 256>>>();                                  // 5
    gemm_ptx_mma_k<<<dim3(NSEGP, 2), 512, SMEM_PTX>>>();      // 6 (one wave)
    pfin2_k<<<CC, 256>>>();                                   // 7
    gemm_mma_k<false><<<dim3((NN + 127) / 128, 2), 256, SMEM_MMA>>>(out, 0, NN); // 8
}